// round 1
// baseline (speedup 1.0000x reference)
#include <cuda_runtime.h>
#include <cuda_bf16.h>
#include <math.h>

// Problem constants
#define NB      65536      // batch
#define DIM     256        // feature dim
#define BANK_N  1000
#define BANK_P  1024       // padded bank
#define TOPK    5

#define P2      132        // smem row pad (floats), multiple of 4 for float4

// Scratch (static device globals — no runtime allocation)
__device__ float g_bn[(size_t)BANK_P * DIM];           // normalized bank (padded, zeros)
__device__ float g_nf[(size_t)NB * DIM];               // weighted neighbor features
__device__ float g_h [(size_t)NB * DIM];               // MLP hidden

// ---------------------------------------------------------------------------
// Kernel 1: normalize feature bank rows, zero the padding rows.
// grid 1024, block 256 (one row per block, one element per thread)
// ---------------------------------------------------------------------------
__global__ void k_bank_norm(const float* __restrict__ bank)
{
    const int r = blockIdx.x;
    const int t = threadIdx.x;
    float x = 0.0f;
    if (r < BANK_N) x = bank[(size_t)r * DIM + t];

    __shared__ float red[8];
    float s = x * x;
    #pragma unroll
    for (int o = 16; o; o >>= 1) s += __shfl_xor_sync(0xffffffffu, s, o);
    if ((t & 31) == 0) red[t >> 5] = s;
    __syncthreads();
    if (t == 0) {
        float tot = 0.0f;
        #pragma unroll
        for (int i = 0; i < 8; i++) tot += red[i];
        red[0] = 1.0f / fmaxf(sqrtf(tot), 1e-12f);
    }
    __syncthreads();
    const float inv = red[0];
    g_bn[(size_t)r * DIM + t] = (r < BANK_N) ? x * inv : 0.0f;
}

// ---------------------------------------------------------------------------
// Kernel 2: per 128-query tile: normalize queries, sims vs full (padded) bank,
// running top-5, softmax, weighted neighbor gather -> g_nf.
// grid 512, block 256. Dynamic smem layout:
//   As[256][P2]  queries, k-major (normalized in place)     135168 B
//   Bs[32][P2]   bank tile, k-major                          16896 B
//   Cs[128][P2]  sims block                                  67584 B
//   Wt[128*5], Ix[128*5]                                      5120 B
// total 224768 B
// ---------------------------------------------------------------------------
__global__ __launch_bounds__(256) void k_sims_topk_nf(
    const float* __restrict__ feat, const float* __restrict__ bank)
{
    extern __shared__ float sm[];
    float* As = sm;                       // 256*P2
    float* Bs = As + 256 * P2;            // 32*P2
    float* Cs = Bs + 32 * P2;             // 128*P2
    float* Wt = Cs + 128 * P2;            // 128*5
    int*   Ix = (int*)(Wt + 128 * TOPK);  // 128*5

    const int t  = threadIdx.x;
    const int q0 = blockIdx.x * 128;
    const int tx = t & 15;
    const int ty = t >> 4;

    // Load 128x256 query tile, transposed to k-major As[k][row]
    {
        const int row = t >> 1;
        const int kbase = (t & 1) * 16;
        #pragma unroll 1
        for (int kb = 0; kb < 8; kb++) {
            const int k0 = kb * 32 + kbase;
            const float4* src = (const float4*)(feat + (size_t)(q0 + row) * DIM + k0);
            #pragma unroll
            for (int j = 0; j < 4; j++) {
                float4 v = src[j];
                const int kk = k0 + 4 * j;
                As[(kk + 0) * P2 + row] = v.x;
                As[(kk + 1) * P2 + row] = v.y;
                As[(kk + 2) * P2 + row] = v.z;
                As[(kk + 3) * P2 + row] = v.w;
            }
        }
    }
    __syncthreads();

    // Normalize rows (threads 0..127 own one row each)
    if (t < 128) {
        float s = 0.0f;
        #pragma unroll 8
        for (int k = 0; k < DIM; k++) { float v = As[k * P2 + t]; s += v * v; }
        const float inv = 1.0f / fmaxf(sqrtf(s), 1e-12f);
        #pragma unroll 8
        for (int k = 0; k < DIM; k++) As[k * P2 + t] *= inv;
    }
    __syncthreads();

    // Running top-5 per row (thread t owns row t, t < 128)
    float tv0 = -3.0e38f, tv1 = -3.0e38f, tv2 = -3.0e38f, tv3 = -3.0e38f, tv4 = -3.0e38f;
    int   ti0 = 0, ti1 = 0, ti2 = 0, ti3 = 0, ti4 = 0;

    #pragma unroll 1
    for (int ct = 0; ct < 8; ct++) {
        float acc[8][8];
        #pragma unroll
        for (int i = 0; i < 8; i++)
            #pragma unroll
            for (int j = 0; j < 8; j++) acc[i][j] = 0.0f;

        #pragma unroll 1
        for (int kt = 0; kt < 8; kt++) {
            __syncthreads();   // protect Bs from previous iteration's readers
            {
                const int c  = t >> 1;
                const int k0 = (t & 1) * 16;
                const float4* src = (const float4*)(g_bn + (size_t)(ct * 128 + c) * DIM + kt * 32 + k0);
                #pragma unroll
                for (int j = 0; j < 4; j++) {
                    float4 v = src[j];
                    const int kk = k0 + 4 * j;
                    Bs[(kk + 0) * P2 + c] = v.x;
                    Bs[(kk + 1) * P2 + c] = v.y;
                    Bs[(kk + 2) * P2 + c] = v.z;
                    Bs[(kk + 3) * P2 + c] = v.w;
                }
            }
            __syncthreads();

            #pragma unroll 8
            for (int k = 0; k < 32; k++) {
                const float* ar = As + (kt * 32 + k) * P2 + ty * 8;
                const float* br = Bs + k * P2 + tx * 8;
                float4 a0 = *(const float4*)(ar);
                float4 a1 = *(const float4*)(ar + 4);
                float4 b0 = *(const float4*)(br);
                float4 b1 = *(const float4*)(br + 4);
                float a[8] = {a0.x, a0.y, a0.z, a0.w, a1.x, a1.y, a1.z, a1.w};
                float b[8] = {b0.x, b0.y, b0.z, b0.w, b1.x, b1.y, b1.z, b1.w};
                #pragma unroll
                for (int i = 0; i < 8; i++)
                    #pragma unroll
                    for (int j = 0; j < 8; j++)
                        acc[i][j] = fmaf(a[i], b[j], acc[i][j]);
            }
        }

        // Store sims block to smem
        #pragma unroll
        for (int i = 0; i < 8; i++) {
            float* cp = Cs + (ty * 8 + i) * P2 + tx * 8;
            *(float4*)(cp)     = make_float4(acc[i][0], acc[i][1], acc[i][2], acc[i][3]);
            *(float4*)(cp + 4) = make_float4(acc[i][4], acc[i][5], acc[i][6], acc[i][7]);
        }
        __syncthreads();

        // Scan this 128-col block updating top-5 (one thread per row)
        if (t < 128) {
            const float* row = Cs + t * P2;
            const int base = ct * 128;
            const int lim = (BANK_N - base < 128) ? (BANK_N - base) : 128;
            for (int c = 0; c < lim; c++) {
                const float s = row[c];
                if (s > tv4) {
                    const int idx = base + c;
                    if (s > tv3) {
                        tv4 = tv3; ti4 = ti3;
                        if (s > tv2) {
                            tv3 = tv2; ti3 = ti2;
                            if (s > tv1) {
                                tv2 = tv1; ti2 = ti1;
                                if (s > tv0) {
                                    tv1 = tv0; ti1 = ti0; tv0 = s; ti0 = idx;
                                } else { tv1 = s; ti1 = idx; }
                            } else { tv2 = s; ti2 = idx; }
                        } else { tv3 = s; ti3 = idx; }
                    } else { tv4 = s; ti4 = idx; }
                }
            }
        }
        __syncthreads();
    }

    // Softmax over top-5 (TEMP = 1)
    if (t < 128) {
        const float m = tv0;
        float e0 = expf(tv0 - m), e1 = expf(tv1 - m), e2 = expf(tv2 - m),
              e3 = expf(tv3 - m), e4 = expf(tv4 - m);
        const float inv = 1.0f / (e0 + e1 + e2 + e3 + e4);
        Wt[t * 5 + 0] = e0 * inv;  Ix[t * 5 + 0] = ti0;
        Wt[t * 5 + 1] = e1 * inv;  Ix[t * 5 + 1] = ti1;
        Wt[t * 5 + 2] = e2 * inv;  Ix[t * 5 + 2] = ti2;
        Wt[t * 5 + 3] = e3 * inv;  Ix[t * 5 + 3] = ti3;
        Wt[t * 5 + 4] = e4 * inv;  Ix[t * 5 + 4] = ti4;
    }
    __syncthreads();

    // Weighted neighbor gather from RAW bank, coalesced along d (t = dim)
    #pragma unroll 1
    for (int r = 0; r < 128; r++) {
        const float w0 = Wt[r * 5 + 0], w1 = Wt[r * 5 + 1], w2 = Wt[r * 5 + 2],
                    w3 = Wt[r * 5 + 3], w4 = Wt[r * 5 + 4];
        const int i0 = Ix[r * 5 + 0], i1 = Ix[r * 5 + 1], i2 = Ix[r * 5 + 2],
                  i3 = Ix[r * 5 + 3], i4 = Ix[r * 5 + 4];
        float v = w0 * bank[(size_t)i0 * DIM + t];
        v = fmaf(w1, bank[(size_t)i1 * DIM + t], v);
        v = fmaf(w2, bank[(size_t)i2 * DIM + t], v);
        v = fmaf(w3, bank[(size_t)i3 * DIM + t], v);
        v = fmaf(w4, bank[(size_t)i4 * DIM + t], v);
        g_nf[(size_t)(q0 + r) * DIM + t] = v;
    }
}

// ---------------------------------------------------------------------------
// Kernel 3: h = relu([feat | nf] @ W1^T + b1)
// grid (512, 2), block 256. K = 512 virtual (first 256 = feat, next 256 = nf).
// ---------------------------------------------------------------------------
__global__ __launch_bounds__(256) void k_mlp1(
    const float* __restrict__ feat, const float* __restrict__ W1,
    const float* __restrict__ b1)
{
    __shared__ float Xs[32 * P2];
    __shared__ float Ws[32 * P2];
    const int t  = threadIdx.x;
    const int tx = t & 15;
    const int ty = t >> 4;
    const int q0 = blockIdx.x * 128;
    const int o0 = blockIdx.y * 128;

    float acc[8][8];
    #pragma unroll
    for (int i = 0; i < 8; i++)
        #pragma unroll
        for (int j = 0; j < 8; j++) acc[i][j] = 0.0f;

    #pragma unroll 1
    for (int kt = 0; kt < 16; kt++) {
        const float* xbase = (kt < 8) ? feat : g_nf;
        const int koff = (kt & 7) * 32;
        __syncthreads();
        {
            const int c  = t >> 1;
            const int k0 = (t & 1) * 16;
            const float4* sx = (const float4*)(xbase + (size_t)(q0 + c) * DIM + koff + k0);
            const float4* sw = (const float4*)(W1 + (size_t)(o0 + c) * (2 * DIM) + kt * 32 + k0);
            #pragma unroll
            for (int j = 0; j < 4; j++) {
                float4 vx = sx[j];
                float4 vw = sw[j];
                const int kk = k0 + 4 * j;
                Xs[(kk + 0) * P2 + c] = vx.x;  Ws[(kk + 0) * P2 + c] = vw.x;
                Xs[(kk + 1) * P2 + c] = vx.y;  Ws[(kk + 1) * P2 + c] = vw.y;
                Xs[(kk + 2) * P2 + c] = vx.z;  Ws[(kk + 2) * P2 + c] = vw.z;
                Xs[(kk + 3) * P2 + c] = vx.w;  Ws[(kk + 3) * P2 + c] = vw.w;
            }
        }
        __syncthreads();
        #pragma unroll 8
        for (int k = 0; k < 32; k++) {
            const float* ar = Xs + k * P2 + ty * 8;
            const float* br = Ws + k * P2 + tx * 8;
            float4 a0 = *(const float4*)(ar);
            float4 a1 = *(const float4*)(ar + 4);
            float4 b0 = *(const float4*)(br);
            float4 b1v = *(const float4*)(br + 4);
            float a[8] = {a0.x, a0.y, a0.z, a0.w, a1.x, a1.y, a1.z, a1.w};
            float b[8] = {b0.x, b0.y, b0.z, b0.w, b1v.x, b1v.y, b1v.z, b1v.w};
            #pragma unroll
            for (int i = 0; i < 8; i++)
                #pragma unroll
                for (int j = 0; j < 8; j++)
                    acc[i][j] = fmaf(a[i], b[j], acc[i][j]);
        }
    }

    float bb[8];
    #pragma unroll
    for (int j = 0; j < 8; j++) bb[j] = b1[o0 + tx * 8 + j];
    #pragma unroll
    for (int i = 0; i < 8; i++) {
        float* dst = g_h + (size_t)(q0 + ty * 8 + i) * DIM + o0 + tx * 8;
        float v[8];
        #pragma unroll
        for (int j = 0; j < 8; j++) v[j] = fmaxf(acc[i][j] + bb[j], 0.0f);
        *(float4*)(dst)     = make_float4(v[0], v[1], v[2], v[3]);
        *(float4*)(dst + 4) = make_float4(v[4], v[5], v[6], v[7]);
    }
}

// ---------------------------------------------------------------------------
// Kernel 4: out = h @ W2^T + b2.  grid (512, 2), block 256, K = 256.
// ---------------------------------------------------------------------------
__global__ __launch_bounds__(256) void k_mlp2(
    const float* __restrict__ W2, const float* __restrict__ b2,
    float* __restrict__ out)
{
    __shared__ float Xs[32 * P2];
    __shared__ float Ws[32 * P2];
    const int t  = threadIdx.x;
    const int tx = t & 15;
    const int ty = t >> 4;
    const int q0 = blockIdx.x * 128;
    const int o0 = blockIdx.y * 128;

    float acc[8][8];
    #pragma unroll
    for (int i = 0; i < 8; i++)
        #pragma unroll
        for (int j = 0; j < 8; j++) acc[i][j] = 0.0f;

    #pragma unroll 1
    for (int kt = 0; kt < 8; kt++) {
        __syncthreads();
        {
            const int c  = t >> 1;
            const int k0 = (t & 1) * 16;
            const float4* sx = (const float4*)(g_h + (size_t)(q0 + c) * DIM + kt * 32 + k0);
            const float4* sw = (const float4*)(W2 + (size_t)(o0 + c) * DIM + kt * 32 + k0);
            #pragma unroll
            for (int j = 0; j < 4; j++) {
                float4 vx = sx[j];
                float4 vw = sw[j];
                const int kk = k0 + 4 * j;
                Xs[(kk + 0) * P2 + c] = vx.x;  Ws[(kk + 0) * P2 + c] = vw.x;
                Xs[(kk + 1) * P2 + c] = vx.y;  Ws[(kk + 1) * P2 + c] = vw.y;
                Xs[(kk + 2) * P2 + c] = vx.z;  Ws[(kk + 2) * P2 + c] = vw.z;
                Xs[(kk + 3) * P2 + c] = vx.w;  Ws[(kk + 3) * P2 + c] = vw.w;
            }
        }
        __syncthreads();
        #pragma unroll 8
        for (int k = 0; k < 32; k++) {
            const float* ar = Xs + k * P2 + ty * 8;
            const float* br = Ws + k * P2 + tx * 8;
            float4 a0 = *(const float4*)(ar);
            float4 a1 = *(const float4*)(ar + 4);
            float4 b0 = *(const float4*)(br);
            float4 b1v = *(const float4*)(br + 4);
            float a[8] = {a0.x, a0.y, a0.z, a0.w, a1.x, a1.y, a1.z, a1.w};
            float b[8] = {b0.x, b0.y, b0.z, b0.w, b1v.x, b1v.y, b1v.z, b1v.w};
            #pragma unroll
            for (int i = 0; i < 8; i++)
                #pragma unroll
                for (int j = 0; j < 8; j++)
                    acc[i][j] = fmaf(a[i], b[j], acc[i][j]);
        }
    }

    float bb[8];
    #pragma unroll
    for (int j = 0; j < 8; j++) bb[j] = b2[o0 + tx * 8 + j];
    #pragma unroll
    for (int i = 0; i < 8; i++) {
        float* dst = out + (size_t)(q0 + ty * 8 + i) * DIM + o0 + tx * 8;
        float v[8];
        #pragma unroll
        for (int j = 0; j < 8; j++) v[j] = acc[i][j] + bb[j];
        *(float4*)(dst)     = make_float4(v[0], v[1], v[2], v[3]);
        *(float4*)(dst + 4) = make_float4(v[4], v[5], v[6], v[7]);
    }
}

// ---------------------------------------------------------------------------
extern "C" void kernel_launch(void* const* d_in, const int* in_sizes, int n_in,
                              void* d_out, int out_size)
{
    const float* feat = (const float*)d_in[0];
    const float* bank = (const float*)d_in[1];
    const float* W1   = (const float*)d_in[2];
    const float* b1   = (const float*)d_in[3];
    const float* W2   = (const float*)d_in[4];
    const float* b2   = (const float*)d_in[5];
    float* out        = (float*)d_out;

    const size_t smem2 = (256 * P2 + 32 * P2 + 128 * P2 + 128 * TOPK) * sizeof(float)
                       + 128 * TOPK * sizeof(int);  // 224768 bytes
    cudaFuncSetAttribute(k_sims_topk_nf,
                         cudaFuncAttributeMaxDynamicSharedMemorySize, (int)smem2);

    k_bank_norm<<<BANK_P, 256>>>(bank);
    k_sims_topk_nf<<<NB / 128, 256, smem2>>>(feat, bank);
    k_mlp1<<<dim3(NB / 128, 2), 256>>>(feat, W1, b1);
    k_mlp2<<<dim3(NB / 128, 2), 256>>>(W2, b2, out);
}

// round 2
// speedup vs baseline: 1.0013x; 1.0013x over previous
#include <cuda_runtime.h>
#include <cuda_bf16.h>
#include <math.h>

// Problem constants
#define NB      65536
#define DIM     256
#define BANK_N  1000
#define BANK_P  1024
#define TOPK    5

typedef unsigned long long u64;

// Scratch
__device__ float g_bn[(size_t)BANK_P * DIM];
__device__ float g_nf[(size_t)NB * DIM];
__device__ float g_h [(size_t)NB * DIM];

// ---- packed f32x2 helpers -------------------------------------------------
__device__ __forceinline__ u64 ffma2(u64 a, u64 b, u64 c) {
    u64 d;
    asm("fma.rn.f32x2 %0, %1, %2, %3;" : "=l"(d) : "l"(a), "l"(b), "l"(c));
    return d;
}
__device__ __forceinline__ u64 dup2(float f) {
    unsigned r = __float_as_uint(f);
    u64 d;
    asm("mov.b64 %0, {%1, %1};" : "=l"(d) : "r"(r));
    return d;
}
__device__ __forceinline__ float f2lo(u64 v) { return __uint_as_float((unsigned)v); }
__device__ __forceinline__ float f2hi(u64 v) { return __uint_as_float((unsigned)(v >> 32)); }

// ---------------------------------------------------------------------------
// Kernel 1: normalize feature bank rows; zero padding rows.
// ---------------------------------------------------------------------------
__global__ void k_bank_norm(const float* __restrict__ bank)
{
    const int r = blockIdx.x;
    const int t = threadIdx.x;
    float x = 0.0f;
    if (r < BANK_N) x = bank[(size_t)r * DIM + t];

    __shared__ float red[8];
    float s = x * x;
    #pragma unroll
    for (int o = 16; o; o >>= 1) s += __shfl_xor_sync(0xffffffffu, s, o);
    if ((t & 31) == 0) red[t >> 5] = s;
    __syncthreads();
    if (t == 0) {
        float tot = 0.0f;
        #pragma unroll
        for (int i = 0; i < 8; i++) tot += red[i];
        red[0] = 1.0f / fmaxf(sqrtf(tot), 1e-12f);
    }
    __syncthreads();
    const float inv = red[0];
    g_bn[(size_t)r * DIM + t] = (r < BANK_N) ? x * inv : 0.0f;
}

// ---------------------------------------------------------------------------
// Kernel 2: sims + top-5 + softmax + weighted gather.
// Block: 256 thr (8 warps as 2x4), tile 128 queries x 256 bank cols per chunk.
// Thread tile 16x8 via f32x2 (8 row-pairs x 8 cols).
// smem (floats): As[256k][128q]   = 32768
//                Bs[32k][256c] / Cs[128][132]  union = 16896
//                Wt[128*5], Ix[128*5]
// ---------------------------------------------------------------------------
#define SIMS_SMEM_FLOATS (32768 + 16896 + 640 + 640)

__global__ __launch_bounds__(256, 1) void k_sims_topk_nf(
    const float* __restrict__ feat, const float* __restrict__ bank)
{
    extern __shared__ float sm[];
    float* As = sm;                    // 256*128
    float* BC = As + 32768;            // Bs (32*256) and Cs (128*132) union
    float* Wt = BC + 16896;            // 128*5
    int*   Ix = (int*)(Wt + 640);      // 128*5

    const int t    = threadIdx.x;
    const int w    = t >> 5;
    const int lane = t & 31;
    const int wy   = w >> 2;           // 0..1  (query rows)
    const int wx   = w & 3;            // 0..3  (bank cols)
    const int lr   = lane >> 3;        // 0..3
    const int lc   = lane & 7;         // 0..7
    const int q0   = blockIdx.x * 128;

    const int RB = wy * 64 + lr * 4;   // row base within 128
    const int CB = wx * 64 + lc * 4;   // col base within 256

    // ---- load 128x256 query tile transposed to As[k][row] ----
    {
        const int row  = t >> 1;
        const int kb0  = (t & 1) * 16;
        #pragma unroll 1
        for (int kb = 0; kb < 8; kb++) {
            const int k0 = kb * 32 + kb0;
            const float4* src = (const float4*)(feat + (size_t)(q0 + row) * DIM + k0);
            #pragma unroll
            for (int j = 0; j < 4; j++) {
                float4 v = src[j];
                const int kk = k0 + 4 * j;
                As[(kk + 0) * 128 + row] = v.x;
                As[(kk + 1) * 128 + row] = v.y;
                As[(kk + 2) * 128 + row] = v.z;
                As[(kk + 3) * 128 + row] = v.w;
            }
        }
    }
    __syncthreads();

    // ---- normalize query rows ----
    if (t < 128) {
        float s = 0.0f;
        #pragma unroll 8
        for (int k = 0; k < DIM; k++) { float v = As[k * 128 + t]; s += v * v; }
        const float inv = 1.0f / fmaxf(sqrtf(s), 1e-12f);
        #pragma unroll 8
        for (int k = 0; k < DIM; k++) As[k * 128 + t] *= inv;
    }
    __syncthreads();

    // ---- running top-5 state (threads 0..127 own one query row each) ----
    float tv0 = -3.0e38f, tv1 = -3.0e38f, tv2 = -3.0e38f, tv3 = -3.0e38f, tv4 = -3.0e38f;
    int   ti0 = 0, ti1 = 0, ti2 = 0, ti3 = 0, ti4 = 0;

    const float* Ap = As + RB;
    float* Bs = BC;
    float* Cs = BC;

    #pragma unroll 1
    for (int ct = 0; ct < 4; ct++) {          // 4 chunks of 256 bank cols
        u64 acc2[8][8];
        #pragma unroll
        for (int i = 0; i < 8; i++)
            #pragma unroll
            for (int j = 0; j < 8; j++) acc2[i][j] = 0ull;

        #pragma unroll 1
        for (int kt = 0; kt < 8; kt++) {      // 8 k-tiles of 32
            __syncthreads();
            // load Bs[32k][256c]: thread t loads bank row (ct*256+t)'s 32 k-vals
            {
                const float* src = g_bn + (size_t)(ct * 256 + t) * DIM + kt * 32;
                #pragma unroll
                for (int j = 0; j < 8; j++) {
                    float4 v = *(const float4*)(src + 4 * j);
                    Bs[(4 * j + 0) * 256 + t] = v.x;
                    Bs[(4 * j + 1) * 256 + t] = v.y;
                    Bs[(4 * j + 2) * 256 + t] = v.z;
                    Bs[(4 * j + 3) * 256 + t] = v.w;
                }
            }
            __syncthreads();

            const float* Bp = Bs + CB;
            #pragma unroll 4
            for (int k = 0; k < 32; k++) {
                const float* ak = Ap + (kt * 32 + k) * 128;
                const float* bk = Bp + k * 256;
                u64 a2[8];
                #pragma unroll
                for (int s = 0; s < 4; s++) {
                    ulonglong2 v = *(const ulonglong2*)(ak + 16 * s);
                    a2[2 * s]     = v.x;
                    a2[2 * s + 1] = v.y;
                }
                float bf[8];
                {
                    float4 b0 = *(const float4*)(bk);
                    float4 b1 = *(const float4*)(bk + 32);
                    bf[0]=b0.x; bf[1]=b0.y; bf[2]=b0.z; bf[3]=b0.w;
                    bf[4]=b1.x; bf[5]=b1.y; bf[6]=b1.z; bf[7]=b1.w;
                }
                u64 b2[8];
                #pragma unroll
                for (int j = 0; j < 8; j++) b2[j] = dup2(bf[j]);
                #pragma unroll
                for (int i = 0; i < 8; i++)
                    #pragma unroll
                    for (int j = 0; j < 8; j++)
                        acc2[i][j] = ffma2(a2[i], b2[j], acc2[i][j]);
            }
        }
        __syncthreads();   // all warps done reading Bs before Cs overwrite

        // two passes of 128 cols: write Cs, scan top-5
        #pragma unroll 1
        for (int pass = 0; pass < 2; pass++) {
            if ((wx >> 1) == pass) {
                const int cb = CB - 128 * pass;   // 0..63 within this pass half
                #pragma unroll
                for (int rp = 0; rp < 8; rp++) {
                    const int row = RB + 16 * (rp >> 1) + 2 * (rp & 1);
                    float4 v0 = make_float4(f2lo(acc2[rp][0]), f2lo(acc2[rp][1]),
                                            f2lo(acc2[rp][2]), f2lo(acc2[rp][3]));
                    float4 v1 = make_float4(f2hi(acc2[rp][0]), f2hi(acc2[rp][1]),
                                            f2hi(acc2[rp][2]), f2hi(acc2[rp][3]));
                    float4 w0 = make_float4(f2lo(acc2[rp][4]), f2lo(acc2[rp][5]),
                                            f2lo(acc2[rp][6]), f2lo(acc2[rp][7]));
                    float4 w1 = make_float4(f2hi(acc2[rp][4]), f2hi(acc2[rp][5]),
                                            f2hi(acc2[rp][6]), f2hi(acc2[rp][7]));
                    *(float4*)(Cs + (row + 0) * 132 + cb)      = v0;
                    *(float4*)(Cs + (row + 1) * 132 + cb)      = v1;
                    *(float4*)(Cs + (row + 0) * 132 + cb + 32) = w0;
                    *(float4*)(Cs + (row + 1) * 132 + cb + 32) = w1;
                }
            }
            __syncthreads();

            if (t < 128) {
                const float* row = Cs + t * 132;
                const int base = ct * 256 + 128 * pass;
                int lim = BANK_N - base; if (lim > 128) lim = 128;
                for (int c = 0; c < lim; c++) {
                    const float s = row[c];
                    if (s > tv4) {
                        const int idx = base + c;
                        if (s > tv3) {
                            tv4 = tv3; ti4 = ti3;
                            if (s > tv2) {
                                tv3 = tv2; ti3 = ti2;
                                if (s > tv1) {
                                    tv2 = tv1; ti2 = ti1;
                                    if (s > tv0) {
                                        tv1 = tv0; ti1 = ti0; tv0 = s; ti0 = idx;
                                    } else { tv1 = s; ti1 = idx; }
                                } else { tv2 = s; ti2 = idx; }
                            } else { tv3 = s; ti3 = idx; }
                        } else { tv4 = s; ti4 = idx; }
                    }
                }
            }
            __syncthreads();
        }
    }

    // ---- softmax over top-5 ----
    if (t < 128) {
        const float m = tv0;
        float e0 = expf(tv0 - m), e1 = expf(tv1 - m), e2 = expf(tv2 - m),
              e3 = expf(tv3 - m), e4 = expf(tv4 - m);
        const float inv = 1.0f / (e0 + e1 + e2 + e3 + e4);
        Wt[t * 5 + 0] = e0 * inv;  Ix[t * 5 + 0] = ti0;
        Wt[t * 5 + 1] = e1 * inv;  Ix[t * 5 + 1] = ti1;
        Wt[t * 5 + 2] = e2 * inv;  Ix[t * 5 + 2] = ti2;
        Wt[t * 5 + 3] = e3 * inv;  Ix[t * 5 + 3] = ti3;
        Wt[t * 5 + 4] = e4 * inv;  Ix[t * 5 + 4] = ti4;
    }
    __syncthreads();

    // ---- weighted neighbor gather (t = dim index) ----
    #pragma unroll 1
    for (int r = 0; r < 128; r++) {
        const float w0 = Wt[r * 5 + 0], w1 = Wt[r * 5 + 1], w2 = Wt[r * 5 + 2],
                    w3 = Wt[r * 5 + 3], w4 = Wt[r * 5 + 4];
        const int i0 = Ix[r * 5 + 0], i1 = Ix[r * 5 + 1], i2 = Ix[r * 5 + 2],
                  i3 = Ix[r * 5 + 3], i4 = Ix[r * 5 + 4];
        float v = w0 * bank[(size_t)i0 * DIM + t];
        v = fmaf(w1, bank[(size_t)i1 * DIM + t], v);
        v = fmaf(w2, bank[(size_t)i2 * DIM + t], v);
        v = fmaf(w3, bank[(size_t)i3 * DIM + t], v);
        v = fmaf(w4, bank[(size_t)i4 * DIM + t], v);
        g_nf[(size_t)(q0 + r) * DIM + t] = v;
    }
}

// ---------------------------------------------------------------------------
// MLP GEMM core shared by mlp1/mlp2. Block tile 128 rows x 256 out cols.
// Xs[32][128], Ws[32][256] static smem (48 KB).
// ---------------------------------------------------------------------------
__global__ __launch_bounds__(256, 1) void k_mlp1(
    const float* __restrict__ feat, const float* __restrict__ W1,
    const float* __restrict__ b1)
{
    __shared__ float Xs[32 * 128];
    __shared__ float Ws[32 * 256];
    const int t    = threadIdx.x;
    const int w    = t >> 5;
    const int lane = t & 31;
    const int wy   = w >> 2;
    const int wx   = w & 3;
    const int lr   = lane >> 3;
    const int lc   = lane & 7;
    const int q0   = blockIdx.x * 128;
    const int RB   = wy * 64 + lr * 4;
    const int CB   = wx * 64 + lc * 4;

    u64 acc2[8][8];
    #pragma unroll
    for (int i = 0; i < 8; i++)
        #pragma unroll
        for (int j = 0; j < 8; j++) acc2[i][j] = 0ull;

    #pragma unroll 1
    for (int kt = 0; kt < 16; kt++) {
        const float* xbase = (kt < 8) ? feat : g_nf;
        const int koff = (kt & 7) * 32;
        __syncthreads();
        {   // Xs: 128 rows x 32 k
            const int row = t >> 1;
            const int k0  = (t & 1) * 16;
            const float4* src = (const float4*)(xbase + (size_t)(q0 + row) * DIM + koff + k0);
            #pragma unroll
            for (int j = 0; j < 4; j++) {
                float4 v = src[j];
                const int kk = k0 + 4 * j;
                Xs[(kk + 0) * 128 + row] = v.x;
                Xs[(kk + 1) * 128 + row] = v.y;
                Xs[(kk + 2) * 128 + row] = v.z;
                Xs[(kk + 3) * 128 + row] = v.w;
            }
            // Ws: 256 out rows x 32 k (thread t = out row)
            const float* wsrc = W1 + (size_t)t * (2 * DIM) + kt * 32;
            #pragma unroll
            for (int j = 0; j < 8; j++) {
                float4 v = *(const float4*)(wsrc + 4 * j);
                Ws[(4 * j + 0) * 256 + t] = v.x;
                Ws[(4 * j + 1) * 256 + t] = v.y;
                Ws[(4 * j + 2) * 256 + t] = v.z;
                Ws[(4 * j + 3) * 256 + t] = v.w;
            }
        }
        __syncthreads();

        const float* Ap = Xs + RB;
        const float* Bp = Ws + CB;
        #pragma unroll 4
        for (int k = 0; k < 32; k++) {
            const float* ak = Ap + k * 128;
            const float* bk = Bp + k * 256;
            u64 a2[8];
            #pragma unroll
            for (int s = 0; s < 4; s++) {
                ulonglong2 v = *(const ulonglong2*)(ak + 16 * s);
                a2[2 * s] = v.x; a2[2 * s + 1] = v.y;
            }
            float bf[8];
            {
                float4 b0v = *(const float4*)(bk);
                float4 b1v = *(const float4*)(bk + 32);
                bf[0]=b0v.x; bf[1]=b0v.y; bf[2]=b0v.z; bf[3]=b0v.w;
                bf[4]=b1v.x; bf[5]=b1v.y; bf[6]=b1v.z; bf[7]=b1v.w;
            }
            u64 b2[8];
            #pragma unroll
            for (int j = 0; j < 8; j++) b2[j] = dup2(bf[j]);
            #pragma unroll
            for (int i = 0; i < 8; i++)
                #pragma unroll
                for (int j = 0; j < 8; j++)
                    acc2[i][j] = ffma2(a2[i], b2[j], acc2[i][j]);
        }
    }

    float bb[8];
    #pragma unroll
    for (int j = 0; j < 8; j++) bb[j] = b1[CB + 32 * (j >> 2) + (j & 3)];

    #pragma unroll
    for (int rp = 0; rp < 8; rp++) {
        const int row0 = q0 + RB + 16 * (rp >> 1) + 2 * (rp & 1);
        float* d0 = g_h + (size_t)row0 * DIM + CB;
        float* d1 = g_h + (size_t)(row0 + 1) * DIM + CB;
        float4 v0 = make_float4(fmaxf(f2lo(acc2[rp][0]) + bb[0], 0.f), fmaxf(f2lo(acc2[rp][1]) + bb[1], 0.f),
                                fmaxf(f2lo(acc2[rp][2]) + bb[2], 0.f), fmaxf(f2lo(acc2[rp][3]) + bb[3], 0.f));
        float4 v1 = make_float4(fmaxf(f2hi(acc2[rp][0]) + bb[0], 0.f), fmaxf(f2hi(acc2[rp][1]) + bb[1], 0.f),
                                fmaxf(f2hi(acc2[rp][2]) + bb[2], 0.f), fmaxf(f2hi(acc2[rp][3]) + bb[3], 0.f));
        float4 u0 = make_float4(fmaxf(f2lo(acc2[rp][4]) + bb[4], 0.f), fmaxf(f2lo(acc2[rp][5]) + bb[5], 0.f),
                                fmaxf(f2lo(acc2[rp][6]) + bb[6], 0.f), fmaxf(f2lo(acc2[rp][7]) + bb[7], 0.f));
        float4 u1 = make_float4(fmaxf(f2hi(acc2[rp][4]) + bb[4], 0.f), fmaxf(f2hi(acc2[rp][5]) + bb[5], 0.f),
                                fmaxf(f2hi(acc2[rp][6]) + bb[6], 0.f), fmaxf(f2hi(acc2[rp][7]) + bb[7], 0.f));
        *(float4*)(d0)      = v0;
        *(float4*)(d1)      = v1;
        *(float4*)(d0 + 32) = u0;
        *(float4*)(d1 + 32) = u1;
    }
}

__global__ __launch_bounds__(256, 1) void k_mlp2(
    const float* __restrict__ W2, const float* __restrict__ b2,
    float* __restrict__ out)
{
    __shared__ float Xs[32 * 128];
    __shared__ float Ws[32 * 256];
    const int t    = threadIdx.x;
    const int w    = t >> 5;
    const int lane = t & 31;
    const int wy   = w >> 2;
    const int wx   = w & 3;
    const int lr   = lane >> 3;
    const int lc   = lane & 7;
    const int q0   = blockIdx.x * 128;
    const int RB   = wy * 64 + lr * 4;
    const int CB   = wx * 64 + lc * 4;

    u64 acc2[8][8];
    #pragma unroll
    for (int i = 0; i < 8; i++)
        #pragma unroll
        for (int j = 0; j < 8; j++) acc2[i][j] = 0ull;

    #pragma unroll 1
    for (int kt = 0; kt < 8; kt++) {
        __syncthreads();
        {
            const int row = t >> 1;
            const int k0  = (t & 1) * 16;
            const float4* src = (const float4*)(g_h + (size_t)(q0 + row) * DIM + kt * 32 + k0);
            #pragma unroll
            for (int j = 0; j < 4; j++) {
                float4 v = src[j];
                const int kk = k0 + 4 * j;
                Xs[(kk + 0) * 128 + row] = v.x;
                Xs[(kk + 1) * 128 + row] = v.y;
                Xs[(kk + 2) * 128 + row] = v.z;
                Xs[(kk + 3) * 128 + row] = v.w;
            }
            const float* wsrc = W2 + (size_t)t * DIM + kt * 32;
            #pragma unroll
            for (int j = 0; j < 8; j++) {
                float4 v = *(const float4*)(wsrc + 4 * j);
                Ws[(4 * j + 0) * 256 + t] = v.x;
                Ws[(4 * j + 1) * 256 + t] = v.y;
                Ws[(4 * j + 2) * 256 + t] = v.z;
                Ws[(4 * j + 3) * 256 + t] = v.w;
            }
        }
        __syncthreads();

        const float* Ap = Xs + RB;
        const float* Bp = Ws + CB;
        #pragma unroll 4
        for (int k = 0; k < 32; k++) {
            const float* ak = Ap + k * 128;
            const float* bk = Bp + k * 256;
            u64 a2[8];
            #pragma unroll
            for (int s = 0; s < 4; s++) {
                ulonglong2 v = *(const ulonglong2*)(ak + 16 * s);
                a2[2 * s] = v.x; a2[2 * s + 1] = v.y;
            }
            float bf[8];
            {
                float4 b0v = *(const float4*)(bk);
                float4 b1v = *(const float4*)(bk + 32);
                bf[0]=b0v.x; bf[1]=b0v.y; bf[2]=b0v.z; bf[3]=b0v.w;
                bf[4]=b1v.x; bf[5]=b1v.y; bf[6]=b1v.z; bf[7]=b1v.w;
            }
            u64 b2[8];
            #pragma unroll
            for (int j = 0; j < 8; j++) b2[j] = dup2(bf[j]);
            #pragma unroll
            for (int i = 0; i < 8; i++)
                #pragma unroll
                for (int j = 0; j < 8; j++)
                    acc2[i][j] = ffma2(a2[i], b2[j], acc2[i][j]);
        }
    }

    float bb[8];
    #pragma unroll
    for (int j = 0; j < 8; j++) bb[j] = b2[CB + 32 * (j >> 2) + (j & 3)];

    #pragma unroll
    for (int rp = 0; rp < 8; rp++) {
        const int row0 = q0 + RB + 16 * (rp >> 1) + 2 * (rp & 1);
        float* d0 = out + (size_t)row0 * DIM + CB;
        float* d1 = out + (size_t)(row0 + 1) * DIM + CB;
        float4 v0 = make_float4(f2lo(acc2[rp][0]) + bb[0], f2lo(acc2[rp][1]) + bb[1],
                                f2lo(acc2[rp][2]) + bb[2], f2lo(acc2[rp][3]) + bb[3]);
        float4 v1 = make_float4(f2hi(acc2[rp][0]) + bb[0], f2hi(acc2[rp][1]) + bb[1],
                                f2hi(acc2[rp][2]) + bb[2], f2hi(acc2[rp][3]) + bb[3]);
        float4 u0 = make_float4(f2lo(acc2[rp][4]) + bb[4], f2lo(acc2[rp][5]) + bb[5],
                                f2lo(acc2[rp][6]) + bb[6], f2lo(acc2[rp][7]) + bb[7]);
        float4 u1 = make_float4(f2hi(acc2[rp][4]) + bb[4], f2hi(acc2[rp][5]) + bb[5],
                                f2hi(acc2[rp][6]) + bb[6], f2hi(acc2[rp][7]) + bb[7]);
        *(float4*)(d0)      = v0;
        *(float4*)(d1)      = v1;
        *(float4*)(d0 + 32) = u0;
        *(float4*)(d1 + 32) = u1;
    }
}

// ---------------------------------------------------------------------------
extern "C" void kernel_launch(void* const* d_in, const int* in_sizes, int n_in,
                              void* d_out, int out_size)
{
    const float* feat = (const float*)d_in[0];
    const float* bank = (const float*)d_in[1];
    const float* W1   = (const float*)d_in[2];
    const float* b1   = (const float*)d_in[3];
    const float* W2   = (const float*)d_in[4];
    const float* b2   = (const float*)d_in[5];
    float* out        = (float*)d_out;

    const size_t smem2 = SIMS_SMEM_FLOATS * sizeof(float);  // 203776 B
    cudaFuncSetAttribute(k_sims_topk_nf,
                         cudaFuncAttributeMaxDynamicSharedMemorySize, (int)smem2);

    k_bank_norm<<<BANK_P, 256>>>(bank);
    k_sims_topk_nf<<<NB / 128, 256, smem2>>>(feat, bank);
    k_mlp1<<<NB / 128, 256>>>(feat, W1, b1);
    k_mlp2<<<NB / 128, 256>>>(W2, b2, out);
}

// round 4
// speedup vs baseline: 1.0788x; 1.0774x over previous
#include <cuda_runtime.h>
#include <cuda_bf16.h>
#include <mma.h>
#include <math.h>

using namespace nvcuda;

#define NB      65536
#define DIM     256
#define BANK_N  1000
#define BANK_P  1024
#define TOPK    5

typedef unsigned int       u32;
typedef unsigned long long u64;

// ---------------- device scratch (static) ----------------
__device__ __align__(16) __nv_bfloat16 g_bn0[BANK_P * DIM];
__device__ __align__(16) __nv_bfloat16 g_bn1[BANK_P * DIM];
__device__ __align__(16) __nv_bfloat16 g_bn2[BANK_P * DIM];
__device__ __align__(16) __nv_bfloat16 g_qn0[(size_t)NB * DIM];
__device__ __align__(16) __nv_bfloat16 g_qn1[(size_t)NB * DIM];
__device__ __align__(16) __nv_bfloat16 g_qn2[(size_t)NB * DIM];
__device__ __align__(16) __nv_bfloat16 g_f0[(size_t)NB * DIM];
__device__ __align__(16) __nv_bfloat16 g_f1[(size_t)NB * DIM];
__device__ __align__(16) __nv_bfloat16 g_nf0[(size_t)NB * DIM];
__device__ __align__(16) __nv_bfloat16 g_nf1[(size_t)NB * DIM];
__device__ __align__(16) __nv_bfloat16 g_h0[(size_t)NB * DIM];
__device__ __align__(16) __nv_bfloat16 g_h1[(size_t)NB * DIM];
__device__ __align__(16) __nv_bfloat16 g_w10[DIM * 2 * DIM];
__device__ __align__(16) __nv_bfloat16 g_w11[DIM * 2 * DIM];
__device__ __align__(16) __nv_bfloat16 g_w20[DIM * DIM];
__device__ __align__(16) __nv_bfloat16 g_w21[DIM * DIM];

// ---------------- elementwise split kernels ----------------
__device__ __forceinline__ float blk_inv_norm(float x) {
    __shared__ float red[8];
    const int t = threadIdx.x;
    float s = x * x;
    #pragma unroll
    for (int o = 16; o; o >>= 1) s += __shfl_xor_sync(0xffffffffu, s, o);
    if ((t & 31) == 0) red[t >> 5] = s;
    __syncthreads();
    if (t == 0) {
        float tot = 0.0f;
        #pragma unroll
        for (int i = 0; i < 8; i++) tot += red[i];
        red[0] = 1.0f / fmaxf(sqrtf(tot), 1e-12f);
    }
    __syncthreads();
    return red[0];
}

__global__ void k_bank_split(const float* __restrict__ bank) {
    const int r = blockIdx.x, t = threadIdx.x;
    float x = (r < BANK_N) ? bank[(size_t)r * DIM + t] : 0.0f;
    const float inv = blk_inv_norm(x);
    float q = (r < BANK_N) ? x * inv : 0.0f;
    __nv_bfloat16 q0 = __float2bfloat16(q);
    float r1 = q - __bfloat162float(q0);
    __nv_bfloat16 q1 = __float2bfloat16(r1);
    __nv_bfloat16 q2 = __float2bfloat16(r1 - __bfloat162float(q1));
    const size_t o = (size_t)r * DIM + t;
    g_bn0[o] = q0; g_bn1[o] = q1; g_bn2[o] = q2;
}

__global__ void k_feat_split(const float* __restrict__ feat) {
    const int r = blockIdx.x, t = threadIdx.x;
    const float x = feat[(size_t)r * DIM + t];
    const float inv = blk_inv_norm(x);
    const float q = x * inv;
    __nv_bfloat16 q0 = __float2bfloat16(q);
    float r1 = q - __bfloat162float(q0);
    __nv_bfloat16 q1 = __float2bfloat16(r1);
    __nv_bfloat16 q2 = __float2bfloat16(r1 - __bfloat162float(q1));
    const size_t o = (size_t)r * DIM + t;
    g_qn0[o] = q0; g_qn1[o] = q1; g_qn2[o] = q2;
    __nv_bfloat16 f0 = __float2bfloat16(x);
    g_f0[o] = f0;
    g_f1[o] = __float2bfloat16(x - __bfloat162float(f0));
}

__global__ void k_w_split(const float* __restrict__ W1, const float* __restrict__ W2) {
    const int i = blockIdx.x * 256 + threadIdx.x;
    if (i < DIM * 2 * DIM) {
        float x = W1[i];
        __nv_bfloat16 h = __float2bfloat16(x);
        g_w10[i] = h;
        g_w11[i] = __float2bfloat16(x - __bfloat162float(h));
    }
    if (i < DIM * DIM) {
        float x = W2[i];
        __nv_bfloat16 h = __float2bfloat16(x);
        g_w20[i] = h;
        g_w21[i] = __float2bfloat16(x - __bfloat162float(h));
    }
}

// ---------------- shared staging helper ----------------
// copy ROWS x 64 bf16 (K-major slab) into smem with row stride LDA=72 elems
#define LDA 72
#define LDC 264

template <int ROWS>
__device__ __forceinline__ void stage64(__nv_bfloat16* dst,
                                        const __nv_bfloat16* __restrict__ src,
                                        int src_ld) {
    const int tid = threadIdx.x;
    #pragma unroll
    for (int i = tid; i < ROWS * 8; i += 256) {
        const int row = i >> 3;
        const int seg = i & 7;
        *(uint4*)(dst + row * LDA + seg * 8) =
            *(const uint4*)(src + (size_t)row * src_ld + seg * 8);
    }
}

typedef wmma::fragment<wmma::matrix_a, 16, 16, 16, __nv_bfloat16, wmma::row_major> FragA;
typedef wmma::fragment<wmma::matrix_b, 16, 16, 16, __nv_bfloat16, wmma::col_major> FragB;
typedef wmma::fragment<wmma::accumulator, 16, 16, 16, float> FragC;

// one 64-deep K slab: accumulate warp tile (2x4 of 16x16) for NTERM term pairs
template <int NTERM>
__device__ __forceinline__ void mma_slab(FragC c[2][4],
                                         __nv_bfloat16* const* At,
                                         __nv_bfloat16* const* Bt,
                                         const int* pa, const int* pb,
                                         int wy, int wx) {
    #pragma unroll
    for (int kk = 0; kk < 64; kk += 16) {
        #pragma unroll
        for (int p = 0; p < NTERM; p++) {
            FragA a[2];
            FragB b[4];
            #pragma unroll
            for (int i = 0; i < 2; i++)
                wmma::load_matrix_sync(a[i], At[pa[p]] + (wy * 32 + i * 16) * LDA + kk, LDA);
            #pragma unroll
            for (int j = 0; j < 4; j++)
                wmma::load_matrix_sync(b[j], Bt[pb[p]] + (wx * 64 + j * 16) * LDA + kk, LDA);
            #pragma unroll
            for (int i = 0; i < 2; i++)
                #pragma unroll
                for (int j = 0; j < 4; j++)
                    wmma::mma_sync(c[i][j], a[i], b[j], c[i][j]);
        }
    }
}

// ---------------- sims + topk + softmax + gather ----------------
// smem bytes: At0@0 At1@9216 At2@18432 | Bt0@27648 Bt1@64512 Bt2@101376
//             Cs@138240 (64x264 f32)   | Wt@205824 Ix@207104  total 208384
#define S_AT(s) ((s) * 9216)
#define S_BT(s) (27648 + (s) * 36864)
#define S_CS    138240
#define S_WTOP  205824
#define S_IXT   207104
#define SIMS_SMEM 208384

__global__ __launch_bounds__(256, 1) void k_sims(const float* __restrict__ bank) {
    extern __shared__ char sm[];
    __nv_bfloat16* At[3] = { (__nv_bfloat16*)(sm + S_AT(0)),
                             (__nv_bfloat16*)(sm + S_AT(1)),
                             (__nv_bfloat16*)(sm + S_AT(2)) };
    __nv_bfloat16* Bt[3] = { (__nv_bfloat16*)(sm + S_BT(0)),
                             (__nv_bfloat16*)(sm + S_BT(1)),
                             (__nv_bfloat16*)(sm + S_BT(2)) };
    float* Cs = (float*)(sm + S_CS);
    float* Wt = (float*)(sm + S_WTOP);
    int*   Ix = (int*)(sm + S_IXT);

    const int t  = threadIdx.x;
    const int w  = t >> 5;
    const int wy = w >> 2;
    const int wx = w & 3;
    const int q0 = blockIdx.x * 64;

    const int pa[6] = {0, 0, 1, 1, 0, 2};
    const int pb[6] = {0, 1, 0, 1, 2, 0};

    float tv0 = -3e38f, tv1 = -3e38f, tv2 = -3e38f, tv3 = -3e38f, tv4 = -3e38f;
    int   ti0 = 0, ti1 = 0, ti2 = 0, ti3 = 0, ti4 = 0;

    #pragma unroll 1
    for (int nt = 0; nt < 4; nt++) {
        FragC c[2][4];
        #pragma unroll
        for (int i = 0; i < 2; i++)
            #pragma unroll
            for (int j = 0; j < 4; j++) wmma::fill_fragment(c[i][j], 0.0f);

        #pragma unroll 1
        for (int kt = 0; kt < 4; kt++) {
            __syncthreads();
            const size_t ao = (size_t)q0 * DIM + kt * 64;
            const size_t bo = (size_t)(nt * 256) * DIM + kt * 64;
            stage64<64>(At[0], g_qn0 + ao, DIM);
            stage64<64>(At[1], g_qn1 + ao, DIM);
            stage64<64>(At[2], g_qn2 + ao, DIM);
            stage64<256>(Bt[0], g_bn0 + bo, DIM);
            stage64<256>(Bt[1], g_bn1 + bo, DIM);
            stage64<256>(Bt[2], g_bn2 + bo, DIM);
            __syncthreads();
            mma_slab<6>(c, At, Bt, pa, pb, wy, wx);
        }

        #pragma unroll
        for (int i = 0; i < 2; i++)
            #pragma unroll
            for (int j = 0; j < 4; j++)
                wmma::store_matrix_sync(Cs + (wy * 32 + i * 16) * LDC + wx * 64 + j * 16,
                                        c[i][j], LDC, wmma::mem_row_major);
        __syncthreads();

        if (t < 64) {
            const float* row = Cs + t * LDC;
            const int base = nt * 256;
            int lim = BANK_N - base; if (lim > 256) lim = 256;
            for (int cc = 0; cc < lim; cc++) {
                const float s = row[cc];
                if (s > tv4) {
                    const int idx = base + cc;
                    if (s > tv3) {
                        tv4 = tv3; ti4 = ti3;
                        if (s > tv2) {
                            tv3 = tv2; ti3 = ti2;
                            if (s > tv1) {
                                tv2 = tv1; ti2 = ti1;
                                if (s > tv0) { tv1 = tv0; ti1 = ti0; tv0 = s; ti0 = idx; }
                                else         { tv1 = s; ti1 = idx; }
                            } else { tv2 = s; ti2 = idx; }
                        } else { tv3 = s; ti3 = idx; }
                    } else { tv4 = s; ti4 = idx; }
                }
            }
        }
        __syncthreads();
    }

    if (t < 64) {
        const float m = tv0;
        float e0 = expf(tv0 - m), e1 = expf(tv1 - m), e2 = expf(tv2 - m),
              e3 = expf(tv3 - m), e4 = expf(tv4 - m);
        const float inv = 1.0f / (e0 + e1 + e2 + e3 + e4);
        Wt[t * 5 + 0] = e0 * inv;  Ix[t * 5 + 0] = ti0;
        Wt[t * 5 + 1] = e1 * inv;  Ix[t * 5 + 1] = ti1;
        Wt[t * 5 + 2] = e2 * inv;  Ix[t * 5 + 2] = ti2;
        Wt[t * 5 + 3] = e3 * inv;  Ix[t * 5 + 3] = ti3;
        Wt[t * 5 + 4] = e4 * inv;  Ix[t * 5 + 4] = ti4;
    }
    __syncthreads();

    // weighted gather (t = dim index 0..255), bf16 split of nf
    #pragma unroll 1
    for (int r = 0; r < 64; r++) {
        const float w0 = Wt[r * 5 + 0], w1 = Wt[r * 5 + 1], w2 = Wt[r * 5 + 2],
                    w3 = Wt[r * 5 + 3], w4 = Wt[r * 5 + 4];
        const int i0 = Ix[r * 5 + 0], i1 = Ix[r * 5 + 1], i2 = Ix[r * 5 + 2],
                  i3 = Ix[r * 5 + 3], i4 = Ix[r * 5 + 4];
        float v = w0 * bank[(size_t)i0 * DIM + t];
        v = fmaf(w1, bank[(size_t)i1 * DIM + t], v);
        v = fmaf(w2, bank[(size_t)i2 * DIM + t], v);
        v = fmaf(w3, bank[(size_t)i3 * DIM + t], v);
        v = fmaf(w4, bank[(size_t)i4 * DIM + t], v);
        const size_t o = (size_t)(q0 + r) * DIM + t;
        __nv_bfloat16 n0 = __float2bfloat16(v);
        g_nf0[o] = n0;
        g_nf1[o] = __float2bfloat16(v - __bfloat162float(n0));
    }
}

// ---------------- MLP kernels ----------------
// smem: Xt0@0 Xt1@9216 | Wt0@18432 Wt1@55296 | Cs@92160 (64x264 f32) total 159744
#define M_XT(s) ((s) * 9216)
#define M_WT(s) (18432 + (s) * 36864)
#define M_CS    92160
#define MLP_SMEM 159744

__global__ __launch_bounds__(256, 1) void k_mlp1(const float* __restrict__ b1) {
    extern __shared__ char sm[];
    __nv_bfloat16* Xt[2] = { (__nv_bfloat16*)(sm + M_XT(0)), (__nv_bfloat16*)(sm + M_XT(1)) };
    __nv_bfloat16* Wt[2] = { (__nv_bfloat16*)(sm + M_WT(0)), (__nv_bfloat16*)(sm + M_WT(1)) };
    float* Cs = (float*)(sm + M_CS);

    const int t  = threadIdx.x;
    const int w  = t >> 5;
    const int wy = w >> 2;
    const int wx = w & 3;
    const int q0 = blockIdx.x * 64;

    const int pa[3] = {0, 0, 1};
    const int pb[3] = {0, 1, 0};

    FragC c[2][4];
    #pragma unroll
    for (int i = 0; i < 2; i++)
        #pragma unroll
        for (int j = 0; j < 4; j++) wmma::fill_fragment(c[i][j], 0.0f);

    #pragma unroll 1
    for (int kt = 0; kt < 8; kt++) {
        __syncthreads();
        const __nv_bfloat16* x0 = (kt < 4) ? g_f0 : g_nf0;
        const __nv_bfloat16* x1 = (kt < 4) ? g_f1 : g_nf1;
        const size_t xo = (size_t)q0 * DIM + (kt & 3) * 64;
        stage64<64>(Xt[0], x0 + xo, DIM);
        stage64<64>(Xt[1], x1 + xo, DIM);
        stage64<256>(Wt[0], g_w10 + kt * 64, 2 * DIM);
        stage64<256>(Wt[1], g_w11 + kt * 64, 2 * DIM);
        __syncthreads();
        mma_slab<3>(c, Xt, Wt, pa, pb, wy, wx);
    }

    #pragma unroll
    for (int i = 0; i < 2; i++)
        #pragma unroll
        for (int j = 0; j < 4; j++)
            wmma::store_matrix_sync(Cs + (wy * 32 + i * 16) * LDC + wx * 64 + j * 16,
                                    c[i][j], LDC, wmma::mem_row_major);
    __syncthreads();

    const float bias = b1[t];
    #pragma unroll 1
    for (int r = 0; r < 64; r++) {
        float v = fmaxf(Cs[r * LDC + t] + bias, 0.0f);
        const size_t o = (size_t)(q0 + r) * DIM + t;
        __nv_bfloat16 h0 = __float2bfloat16(v);
        g_h0[o] = h0;
        g_h1[o] = __float2bfloat16(v - __bfloat162float(h0));
    }
}

__global__ __launch_bounds__(256, 1) void k_mlp2(const float* __restrict__ b2,
                                                 float* __restrict__ out) {
    extern __shared__ char sm[];
    __nv_bfloat16* Xt[2] = { (__nv_bfloat16*)(sm + M_XT(0)), (__nv_bfloat16*)(sm + M_XT(1)) };
    __nv_bfloat16* Wt[2] = { (__nv_bfloat16*)(sm + M_WT(0)), (__nv_bfloat16*)(sm + M_WT(1)) };
    float* Cs = (float*)(sm + M_CS);

    const int t  = threadIdx.x;
    const int w  = t >> 5;
    const int wy = w >> 2;
    const int wx = w & 3;
    const int q0 = blockIdx.x * 64;

    const int pa[3] = {0, 0, 1};
    const int pb[3] = {0, 1, 0};

    FragC c[2][4];
    #pragma unroll
    for (int i = 0; i < 2; i++)
        #pragma unroll
        for (int j = 0; j < 4; j++) wmma::fill_fragment(c[i][j], 0.0f);

    #pragma unroll 1
    for (int kt = 0; kt < 4; kt++) {
        __syncthreads();
        const size_t xo = (size_t)q0 * DIM + kt * 64;
        stage64<64>(Xt[0], g_h0 + xo, DIM);
        stage64<64>(Xt[1], g_h1 + xo, DIM);
        stage64<256>(Wt[0], g_w20 + kt * 64, DIM);
        stage64<256>(Wt[1], g_w21 + kt * 64, DIM);
        __syncthreads();
        mma_slab<3>(c, Xt, Wt, pa, pb, wy, wx);
    }

    #pragma unroll
    for (int i = 0; i < 2; i++)
        #pragma unroll
        for (int j = 0; j < 4; j++)
            wmma::store_matrix_sync(Cs + (wy * 32 + i * 16) * LDC + wx * 64 + j * 16,
                                    c[i][j], LDC, wmma::mem_row_major);
    __syncthreads();

    const float bias = b2[t];
    #pragma unroll 1
    for (int r = 0; r < 64; r++)
        out[(size_t)(q0 + r) * DIM + t] = Cs[r * LDC + t] + bias;
}

// ---------------------------------------------------------------------------
extern "C" void kernel_launch(void* const* d_in, const int* in_sizes, int n_in,
                              void* d_out, int out_size) {
    const float* feat = (const float*)d_in[0];
    const float* bank = (const float*)d_in[1];
    const float* W1   = (const float*)d_in[2];
    const float* b1   = (const float*)d_in[3];
    const float* W2   = (const float*)d_in[4];
    const float* b2   = (const float*)d_in[5];
    float* out        = (float*)d_out;

    cudaFuncSetAttribute(k_sims, cudaFuncAttributeMaxDynamicSharedMemorySize, SIMS_SMEM);
    cudaFuncSetAttribute(k_mlp1, cudaFuncAttributeMaxDynamicSharedMemorySize, MLP_SMEM);
    cudaFuncSetAttribute(k_mlp2, cudaFuncAttributeMaxDynamicSharedMemorySize, MLP_SMEM);

    k_bank_split<<<BANK_P, 256>>>(bank);
    k_feat_split<<<NB, 256>>>(feat);
    k_w_split<<<(DIM * 2 * DIM + 255) / 256, 256>>>(W1, W2);
    k_sims<<<NB / 64, 256, SIMS_SMEM>>>(bank);
    k_mlp1<<<NB / 64, 256, MLP_SMEM>>>(b1);
    k_mlp2<<<NB / 64, 256, MLP_SMEM>>>(b2, out);
}